// round 8
// baseline (speedup 1.0000x reference)
#include <cuda_runtime.h>
#include <cuda_bf16.h>
#include <cstdint>
#include <stdint.h>

// ---------------- problem constants ----------------
#define NB   32          // batch
#define TT   2048        // time steps
#define BT   65536       // NB*TT
#define CND  128         // condition channels
#define QV   256         // quantization channels
#define ACH  192         // gru_a hidden
#define GA   576         // 3*ACH
#define BCH  32          // gru_b hidden
#define GB   96          // 3*BCH
#define NOUT 672         // GA + GB (fused input-proj width)

// ---------------- device scratch (no allocations allowed) ----------------
__device__ float  g_embT[QV * QV];            // emb transposed [c][q]
__device__ float  g_E[3 * QV * GA];           // lerp tables: emb @ W_seg^T, [seg][q][o]
__device__ float4 g_WinT4[32 * NOUT];         // input-proj weights, [k4][o] as float4 over k
__device__ float4 g_WhhA4[48 * GA];           // w_hh_a repacked [k4][o]
__device__ float4 g_W1T4[48 * GB];            // w_ih_b h-part repacked [k4][o]
__device__ float  g_fcwT[32 * 512];           // fc_w transposed [k][j]
__device__ float  g_giA[BT * GA];             // GRU-A input projections (151 MB)
__device__ float  g_giB[BT * GB];             // GRU-B input projections (25 MB)
__device__ float  g_hA[BT * ACH];             // GRU-A hidden states (50 MB)
__device__ float  g_hB[BT * BCH];             // GRU-B hidden states (17 MB)

// ---------------- fast activations ----------------
__device__ __forceinline__ float sigm_f(float x) {
    return __fdividef(1.0f, 1.0f + __expf(-x));
}
__device__ __forceinline__ float tanh_f(float x) {
    return 1.0f - __fdividef(2.0f, 1.0f + __expf(2.0f * x));
}

__device__ __forceinline__ unsigned smem_u32(const void* p) {
    unsigned a;
    asm("{ .reg .u64 t; cvta.to.shared.u64 t, %1; cvt.u32.u64 %0, t; }"
        : "=r"(a) : "l"(p));
    return a;
}
__device__ __forceinline__ unsigned ctarank() {
    unsigned r;
    asm("mov.u32 %0, %%cluster_ctarank;" : "=r"(r));
    return r;
}
__device__ __forceinline__ void st_peer_f32(unsigned local_addr, unsigned peer, float v) {
    unsigned ra;
    asm volatile("mapa.shared::cluster.u32 %0, %1, %2;" : "=r"(ra) : "r"(local_addr), "r"(peer));
    asm volatile("st.shared::cluster.f32 [%0], %1;" :: "r"(ra), "f"(v) : "memory");
}
__device__ __forceinline__ void mbar_arrive_cluster(unsigned local_mbar, unsigned target) {
    unsigned ra;
    asm volatile("mapa.shared::cluster.u32 %0, %1, %2;" : "=r"(ra) : "r"(local_mbar), "r"(target));
    asm volatile("mbarrier.arrive.release.cluster.shared::cluster.b64 _, [%0];"
                 :: "r"(ra) : "memory");
}
__device__ __forceinline__ void mbar_wait_parity(unsigned mbar, unsigned parity) {
    asm volatile(
        "{\n\t"
        ".reg .pred P;\n\t"
        "WAIT_%=:\n\t"
        "mbarrier.try_wait.parity.acquire.cluster.shared::cta.b64 P, [%0], %1, 0x989680;\n\t"
        "@!P bra WAIT_%=;\n\t"
        "}"
        :: "r"(mbar), "r"(parity) : "memory");
}
__device__ __forceinline__ void cluster_bar() {
    asm volatile("barrier.cluster.arrive.aligned;" ::: "memory");
    asm volatile("barrier.cluster.wait.aligned;" ::: "memory");
}

// ---------------- prep 1: transposes / repacks ----------------
__global__ void k_prep1(const float* __restrict__ emb,
                        const float* __restrict__ wiha,
                        const float* __restrict__ whha,
                        const float* __restrict__ wihb,
                        const float* __restrict__ fcw) {
    int i = blockIdx.x * blockDim.x + threadIdx.x;
    int stride = gridDim.x * blockDim.x;
    for (int idx = i; idx < QV * QV; idx += stride) {
        int q = idx >> 8, c = idx & 255;
        g_embT[c * QV + q] = emb[idx];
    }
    for (int idx = i; idx < 32 * NOUT; idx += stride) {
        int k4 = idx / NOUT, o = idx % NOUT;
        const float* src = (o < GA) ? (wiha + o * 896 + 4 * k4)
                                    : (wihb + (o - GA) * 320 + 192 + 4 * k4);
        g_WinT4[idx] = make_float4(src[0], src[1], src[2], src[3]);
    }
    for (int idx = i; idx < 48 * GA; idx += stride) {
        int k4 = idx / GA, o = idx % GA;
        const float* src = whha + o * ACH + 4 * k4;
        g_WhhA4[idx] = make_float4(src[0], src[1], src[2], src[3]);
    }
    for (int idx = i; idx < 48 * GB; idx += stride) {
        int k4 = idx / GB, o = idx % GB;
        const float* src = wihb + o * 320 + 4 * k4;
        g_W1T4[idx] = make_float4(src[0], src[1], src[2], src[3]);
    }
    for (int idx = i; idx < 32 * 512; idx += stride) {
        int k = idx >> 9, j = idx & 511;
        g_fcwT[idx] = fcw[j * 32 + k];
    }
}

// ---------------- prep 2: lerp tables E_seg = emb @ W_seg^T ----------------
__global__ void k_prep2(const float* __restrict__ wiha) {
    int warp = (blockIdx.x * blockDim.x + threadIdx.x) >> 5;
    int lane = threadIdx.x & 31;
    if (warp >= 3 * GA * 8) return;
    int s = warp / (GA * 8);
    int rem = warp % (GA * 8);
    int o = rem >> 3;
    int q = (rem & 7) * 32 + lane;
    const float* wrow = wiha + o * 896 + 128 + s * 256;
    const float* ecol = g_embT + q;
    float acc = 0.f;
#pragma unroll 8
    for (int c = 0; c < 256; c++)
        acc = fmaf(wrow[c], ecol[c * QV], acc);
    g_E[s * QV * GA + q * GA + o] = acc;
}

// ---------------- gi_a (+ gi_b f-part): [BT,128] x [128,672] + lerps ------
__global__ void __launch_bounds__(256) k_giA(const float* __restrict__ f,
                                             const float* __restrict__ p,
                                             const float* __restrict__ sp,
                                             const float* __restrict__ ep) {
    __shared__ __align__(16) float sf[32][128];
    __shared__ int   slo[3][32];
    __shared__ float sfr[3][32];
    int tid = threadIdx.x;
    int row0 = blockIdx.x * 32;
    for (int i = tid; i < 32 * 128; i += 256)
        sf[i >> 7][i & 127] = f[row0 * 128 + i];
    if (tid < 96) {
        int j = tid >> 5, m = tid & 31;
        const float* src = (j == 0) ? p : ((j == 1) ? sp : ep);
        float raw = src[row0 + m] * 255.0f;
        int lo = (int)floorf(raw);
        lo = min(max(lo, 0), 254);
        slo[j][m] = lo;
        sfr[j][m] = raw - (float)lo;
    }
    __syncthreads();

    for (int o = tid; o < NOUT; o += 256) {
        float acc[32];
#pragma unroll
        for (int m = 0; m < 32; m++) acc[m] = 0.f;
        for (int k4 = 0; k4 < 32; k4++) {
            float4 w = g_WinT4[k4 * NOUT + o];
#pragma unroll
            for (int m = 0; m < 32; m++) {
                float4 fv = *reinterpret_cast<const float4*>(&sf[m][k4 * 4]);
                acc[m] = fmaf(w.x, fv.x, acc[m]);
                acc[m] = fmaf(w.y, fv.y, acc[m]);
                acc[m] = fmaf(w.z, fv.z, acc[m]);
                acc[m] = fmaf(w.w, fv.w, acc[m]);
            }
        }
        if (o < GA) {
#pragma unroll
            for (int m = 0; m < 32; m++) {
                float v = acc[m];
#pragma unroll
                for (int j = 0; j < 3; j++) {
                    const float* E = g_E + j * QV * GA;
                    int lo = slo[j][m];
                    float fr = sfr[j][m];
                    float e0 = E[lo * GA + o];
                    float e1 = E[(lo + 1) * GA + o];
                    v += e0 + fr * (e1 - e0);
                }
                g_giA[(row0 + m) * GA + o] = v;
            }
        } else {
#pragma unroll
            for (int m = 0; m < 32; m++)
                g_giB[(row0 + m) * GB + (o - GA)] = acc[m];
        }
    }
}

// ---------------- GRU-A scan: 4-CTA cluster per batch, weights in REGISTERS
// CTA rank r owns channels [r*48, r*48+48). 576 threads: quad j = tid>>2
// handles gate-row (g = j/48, cl = j%48), lane q = tid&3 does k-slice
// [q*48, q*48+48) with 12 float4 weights held in registers.
__global__ void __cluster_dims__(4, 1, 1) __launch_bounds__(576, 1) k_gruA4() {
    __shared__ __align__(16) float hbuf[2 * ACH];   // double-buffered full h
    __shared__ float s_u[96];                       // r,z pre-activations
    __shared__ float s_gin[48];
    __shared__ float s_ghn[48];
    __shared__ __align__(8) unsigned long long mbar;

    int tid = threadIdx.x;
    unsigned rank = ctarank();
    int b = blockIdx.x >> 2;
    int j = tid >> 2;          // quad 0..143
    int q = tid & 3;           // k-slice
    int g = j / 48;            // gate
    int cl = j - g * 48;       // local channel
    int chan = (int)rank * 48 + cl;
    int grow = g * ACH + chan; // global gate row 0..575

    // weights -> registers (12 float4 = 48 floats, k-slices q*12 .. q*12+11)
    float4 wreg[12];
#pragma unroll
    for (int i = 0; i < 12; i++)
        wreg[i] = g_WhhA4[(q * 12 + i) * GA + grow];

    for (int i = tid; i < 2 * ACH; i += 576) hbuf[i] = 0.f;
    if (tid == 0)
        asm volatile("mbarrier.init.shared.b64 [%0], %1;"
                     :: "r"(smem_u32(&mbar)), "r"(192) : "memory");
    __syncthreads();
    cluster_bar();             // peers' hbuf zeros + mbarrier inits visible

    unsigned mbar_addr = smem_u32(&mbar);
    unsigned hbuf_addr = smem_u32(hbuf);
    int base = b * TT;
    float giv = 0.f;
    if (q == 0) giv = g_giA[base * GA + grow];
    int wch = (int)rank * 48 + tid;   // writer channel (valid for tid<48)

    for (int t = 0; t < TT; t++) {
        int row = base + t;
        float givn = 0.f;
        if (q == 0 && t + 1 < TT) givn = g_giA[(row + 1) * GA + grow];

        const float4* hc = reinterpret_cast<const float4*>(hbuf + (t & 1) * ACH) + q * 12;
        float a0 = 0.f, a1 = 0.f, a2 = 0.f, a3 = 0.f;
#pragma unroll
        for (int i = 0; i < 12; i++) {
            float4 w = wreg[i];
            float4 hv = hc[i];
            a0 = fmaf(w.x, hv.x, a0);
            a1 = fmaf(w.y, hv.y, a1);
            a2 = fmaf(w.z, hv.z, a2);
            a3 = fmaf(w.w, hv.w, a3);
        }
        float v = (a0 + a1) + (a2 + a3);
        v += __shfl_xor_sync(0xffffffffu, v, 1);
        v += __shfl_xor_sync(0xffffffffu, v, 2);
        if (q == 0) {
            if (g < 2) s_u[j] = giv + v;
            else { s_gin[cl] = giv; s_ghn[cl] = v; }
        }
        __syncthreads();       // gates writers on ALL local dot reads of buf(t&1)
        if (tid < 48) {
            float r = sigm_f(s_u[tid]);
            float z = sigm_f(s_u[48 + tid]);
            float n = tanh_f(s_gin[tid] + r * s_ghn[tid]);
            float hp = hbuf[(t & 1) * ACH + wch];
            float hn = n + z * (hp - n);
            int off = ((t + 1) & 1) * ACH + wch;
            hbuf[off] = hn;
            unsigned addr = hbuf_addr + (unsigned)off * 4u;
#pragma unroll
            for (int r4 = 0; r4 < 4; r4++)
                if (r4 != (int)rank) st_peer_f32(addr, (unsigned)r4, hn);
            g_hA[row * ACH + wch] = hn;
#pragma unroll
            for (int r4 = 0; r4 < 4; r4++)
                mbar_arrive_cluster(mbar_addr, (unsigned)r4);
        }
        mbar_wait_parity(mbar_addr, (unsigned)(t & 1));
        giv = givn;
    }
    cluster_bar();             // no CTA exits while peers may still target it
}

// ---------------- gi_b += h_a @ W1^T : [BT,192] x [192,96] ----------------
__global__ void __launch_bounds__(96) k_giBadd() {
    __shared__ __align__(16) float sh[32][192];
    int tid = threadIdx.x;
    int row0 = blockIdx.x * 32;
    for (int i = tid; i < 32 * 192; i += 96)
        sh[i / 192][i % 192] = g_hA[row0 * 192 + i];
    __syncthreads();
    int o = tid;
    float acc[32];
#pragma unroll
    for (int m = 0; m < 32; m++) acc[m] = 0.f;
    for (int k4 = 0; k4 < 48; k4++) {
        float4 w = g_W1T4[k4 * GB + o];
#pragma unroll
        for (int m = 0; m < 32; m++) {
            float4 hv = *reinterpret_cast<const float4*>(&sh[m][k4 * 4]);
            acc[m] = fmaf(w.x, hv.x, acc[m]);
            acc[m] = fmaf(w.y, hv.y, acc[m]);
            acc[m] = fmaf(w.z, hv.z, acc[m]);
            acc[m] = fmaf(w.w, hv.w, acc[m]);
        }
    }
#pragma unroll
    for (int m = 0; m < 32; m++) {
        int idx = (row0 + m) * GB + o;
        g_giB[idx] += acc[m];
    }
}

// ---------------- GRU-B scan: 32 blocks, 96 threads, depth-4 gi prefetch --
__global__ void __launch_bounds__(96) k_gruB(const float* __restrict__ whhb) {
    __shared__ __align__(16) float4 wt4[8 * GB];
    __shared__ __align__(16) float h[BCH];
    __shared__ float gh[GB];
    __shared__ float gi[GB];
    int tid = threadIdx.x;
    int b = blockIdx.x;
    for (int i = tid; i < 8 * GB; i += 96) {
        int k4 = i / GB, o = i % GB;
        const float* src = whhb + o * 32 + 4 * k4;
        wt4[i] = make_float4(src[0], src[1], src[2], src[3]);
    }
    if (tid < BCH) h[tid] = 0.f;
    __syncthreads();
    int base = b * TT;
    float pre[4];
#pragma unroll
    for (int j = 0; j < 4; j++)
        pre[j] = g_giB[(base + j) * GB + tid];

    for (int t = 0; t < TT; t += 4) {
#pragma unroll
        for (int j = 0; j < 4; j++) {
            int tt = t + j;
            int row = base + tt;
            float givn = (tt + 4 < TT) ? g_giB[(row + 4) * GB + tid] : 0.f;
            float a0 = 0.f, a1 = 0.f;
#pragma unroll
            for (int k4 = 0; k4 < 8; k4++) {
                float4 w  = wt4[k4 * GB + tid];
                float4 hv = *reinterpret_cast<const float4*>(&h[4 * k4]);
                a0 = fmaf(w.x, hv.x, a0);
                a0 = fmaf(w.y, hv.y, a0);
                a1 = fmaf(w.z, hv.z, a1);
                a1 = fmaf(w.w, hv.w, a1);
            }
            gh[tid] = a0 + a1;
            gi[tid] = pre[j];
            __syncthreads();
            if (tid < BCH) {
                float r = sigm_f(gi[tid] + gh[tid]);
                float z = sigm_f(gi[BCH + tid] + gh[BCH + tid]);
                float n = tanh_f(gi[2 * BCH + tid] + r * gh[2 * BCH + tid]);
                float hn = n + z * (h[tid] - n);
                h[tid] = hn;
                g_hB[row * BCH + tid] = hn;
            }
            __syncthreads();
            pre[j] = givn;
        }
    }
}

// ---------------- output: tanh(h_b @ fc_w^T + b) * a, pair-sum ------------
__global__ void __launch_bounds__(256) k_out(const float* __restrict__ av,
                                             const float* __restrict__ fcb,
                                             float* __restrict__ out) {
    __shared__ __align__(16) float shb[32][32];
    int tid = threadIdx.x;
    int row0 = blockIdx.x * 32;
    for (int i = tid; i < 32 * 32; i += 256)
        shb[i >> 5][i & 31] = g_hB[row0 * 32 + i];
    __syncthreads();
    int q = tid;
    float2 wreg[32];
#pragma unroll
    for (int k = 0; k < 32; k++)
        wreg[k] = *reinterpret_cast<const float2*>(g_fcwT + k * 512 + 2 * q);
    float b0 = fcb[2 * q], b1 = fcb[2 * q + 1];
    float av0 = av[2 * q], av1 = av[2 * q + 1];
    for (int m = 0; m < 32; m++) {
        float d0 = b0, d1 = b1;
        const float4* hp = reinterpret_cast<const float4*>(shb[m]);
#pragma unroll
        for (int k4 = 0; k4 < 8; k4++) {
            float4 hv = hp[k4];
            d0 = fmaf(hv.x, wreg[4 * k4 + 0].x, d0);
            d0 = fmaf(hv.y, wreg[4 * k4 + 1].x, d0);
            d0 = fmaf(hv.z, wreg[4 * k4 + 2].x, d0);
            d0 = fmaf(hv.w, wreg[4 * k4 + 3].x, d0);
            d1 = fmaf(hv.x, wreg[4 * k4 + 0].y, d1);
            d1 = fmaf(hv.y, wreg[4 * k4 + 1].y, d1);
            d1 = fmaf(hv.z, wreg[4 * k4 + 2].y, d1);
            d1 = fmaf(hv.w, wreg[4 * k4 + 3].y, d1);
        }
        float t0 = tanh_f(d0);
        float t1 = tanh_f(d1);
        out[(row0 + m) * 256 + q] = av0 * t0 + av1 * t1;
    }
}

// ---------------- launch ----------------
extern "C" void kernel_launch(void* const* d_in, const int* in_sizes, int n_in,
                              void* d_out, int out_size) {
    const float* f    = (const float*)d_in[0];
    const float* p    = (const float*)d_in[1];
    const float* sp   = (const float*)d_in[2];
    const float* ep   = (const float*)d_in[3];
    const float* emb  = (const float*)d_in[4];
    const float* wiha = (const float*)d_in[5];
    const float* whha = (const float*)d_in[6];
    const float* wihb = (const float*)d_in[7];
    const float* whhb = (const float*)d_in[8];
    const float* av   = (const float*)d_in[9];
    const float* fcw  = (const float*)d_in[10];
    const float* fcb  = (const float*)d_in[11];
    float* out = (float*)d_out;

    k_prep1<<<256, 256>>>(emb, wiha, whha, wihb, fcw);
    k_prep2<<<1728, 256>>>(wiha);
    k_giA<<<BT / 32, 256>>>(f, p, sp, ep);
    k_gruA4<<<4 * NB, 576>>>();
    k_giBadd<<<BT / 32, GB>>>();
    k_gruB<<<NB, GB>>>(whhb);
    k_out<<<BT / 32, 256>>>(av, fcb, out);
}

// round 10
// speedup vs baseline: 1.2748x; 1.2748x over previous
#include <cuda_runtime.h>
#include <cuda_bf16.h>
#include <cstdint>
#include <stdint.h>

// ---------------- problem constants ----------------
#define NB   32          // batch
#define TT   2048        // time steps
#define BT   65536       // NB*TT
#define CND  128         // condition channels
#define QV   256         // quantization channels
#define ACH  192         // gru_a hidden
#define GA   576         // 3*ACH
#define BCH  32          // gru_b hidden
#define GB   96          // 3*BCH
#define NOUT 672         // GA + GB (fused input-proj width)

#define W_REG  16        // float4 weights per thread in registers
#define W_SMEM 8         // float4 weights per thread streamed from SMEM
#define HSTRIDE 208      // h parity stride (96 + pad to 112 + 96) floats

// ---------------- device scratch (no allocations allowed) ----------------
__device__ float  g_embT[QV * QV];            // emb transposed [c][q]
__device__ float  g_E[3 * QV * GA];           // lerp tables: emb @ W_seg^T, [seg][q][o]
__device__ float4 g_WinT4[32 * NOUT];         // input-proj weights, [k4][o] as float4 over k
__device__ float4 g_WhhA4[48 * GA];           // w_hh_a repacked [k4][o]
__device__ float4 g_W1T4[48 * GB];            // w_ih_b h-part repacked [k4][o]
__device__ float  g_fcwT[32 * 512];           // fc_w transposed [k][j]
__device__ float  g_giA[BT * GA];             // GRU-A input projections (151 MB)
__device__ float  g_giB[BT * GB];             // GRU-B input projections (25 MB)
__device__ float  g_hA[BT * ACH];             // GRU-A hidden states (50 MB)
__device__ float  g_hB[BT * BCH];             // GRU-B hidden states (17 MB)

// ---------------- fast activations ----------------
__device__ __forceinline__ float sigm_f(float x) {
    return __fdividef(1.0f, 1.0f + __expf(-x));
}
__device__ __forceinline__ float tanh_f(float x) {
    return 1.0f - __fdividef(2.0f, 1.0f + __expf(2.0f * x));
}

__device__ __forceinline__ unsigned smem_u32(const void* p) {
    unsigned a;
    asm("{ .reg .u64 t; cvta.to.shared.u64 t, %1; cvt.u32.u64 %0, t; }"
        : "=r"(a) : "l"(p));
    return a;
}
__device__ __forceinline__ unsigned ctarank() {
    unsigned r;
    asm("mov.u32 %0, %%cluster_ctarank;" : "=r"(r));
    return r;
}
__device__ __forceinline__ void st_peer_f32(unsigned local_addr, unsigned peer, float v) {
    unsigned ra;
    asm volatile("mapa.shared::cluster.u32 %0, %1, %2;" : "=r"(ra) : "r"(local_addr), "r"(peer));
    asm volatile("st.shared::cluster.f32 [%0], %1;" :: "r"(ra), "f"(v) : "memory");
}
__device__ __forceinline__ void cluster_bar() {
    asm volatile("barrier.cluster.arrive.aligned;" ::: "memory");
    asm volatile("barrier.cluster.wait.aligned;" ::: "memory");
}

// ---------------- prep 1: transposes / repacks ----------------
__global__ void k_prep1(const float* __restrict__ emb,
                        const float* __restrict__ wiha,
                        const float* __restrict__ whha,
                        const float* __restrict__ wihb,
                        const float* __restrict__ fcw) {
    int i = blockIdx.x * blockDim.x + threadIdx.x;
    int stride = gridDim.x * blockDim.x;
    for (int idx = i; idx < QV * QV; idx += stride) {
        int q = idx >> 8, c = idx & 255;
        g_embT[c * QV + q] = emb[idx];
    }
    for (int idx = i; idx < 32 * NOUT; idx += stride) {
        int k4 = idx / NOUT, o = idx % NOUT;
        const float* src = (o < GA) ? (wiha + o * 896 + 4 * k4)
                                    : (wihb + (o - GA) * 320 + 192 + 4 * k4);
        g_WinT4[idx] = make_float4(src[0], src[1], src[2], src[3]);
    }
    for (int idx = i; idx < 48 * GA; idx += stride) {
        int k4 = idx / GA, o = idx % GA;
        const float* src = whha + o * ACH + 4 * k4;
        g_WhhA4[idx] = make_float4(src[0], src[1], src[2], src[3]);
    }
    for (int idx = i; idx < 48 * GB; idx += stride) {
        int k4 = idx / GB, o = idx % GB;
        const float* src = wihb + o * 320 + 4 * k4;
        g_W1T4[idx] = make_float4(src[0], src[1], src[2], src[3]);
    }
    for (int idx = i; idx < 32 * 512; idx += stride) {
        int k = idx >> 9, j = idx & 511;
        g_fcwT[idx] = fcw[j * 32 + k];
    }
}

// ---------------- prep 2: lerp tables E_seg = emb @ W_seg^T ----------------
__global__ void k_prep2(const float* __restrict__ wiha) {
    int warp = (blockIdx.x * blockDim.x + threadIdx.x) >> 5;
    int lane = threadIdx.x & 31;
    if (warp >= 3 * GA * 8) return;
    int s = warp / (GA * 8);
    int rem = warp % (GA * 8);
    int o = rem >> 3;
    int q = (rem & 7) * 32 + lane;
    const float* wrow = wiha + o * 896 + 128 + s * 256;
    const float* ecol = g_embT + q;
    float acc = 0.f;
#pragma unroll 8
    for (int c = 0; c < 256; c++)
        acc = fmaf(wrow[c], ecol[c * QV], acc);
    g_E[s * QV * GA + q * GA + o] = acc;
}

// ---------------- gi_a (+ gi_b f-part): [BT,128] x [128,672] + lerps ------
__global__ void __launch_bounds__(256) k_giA(const float* __restrict__ f,
                                             const float* __restrict__ p,
                                             const float* __restrict__ sp,
                                             const float* __restrict__ ep) {
    __shared__ __align__(16) float sf[32][128];
    __shared__ int   slo[3][32];
    __shared__ float sfr[3][32];
    int tid = threadIdx.x;
    int row0 = blockIdx.x * 32;
    for (int i = tid; i < 32 * 128; i += 256)
        sf[i >> 7][i & 127] = f[row0 * 128 + i];
    if (tid < 96) {
        int j = tid >> 5, m = tid & 31;
        const float* src = (j == 0) ? p : ((j == 1) ? sp : ep);
        float raw = src[row0 + m] * 255.0f;
        int lo = (int)floorf(raw);
        lo = min(max(lo, 0), 254);
        slo[j][m] = lo;
        sfr[j][m] = raw - (float)lo;
    }
    __syncthreads();

    for (int o = tid; o < NOUT; o += 256) {
        float acc[32];
#pragma unroll
        for (int m = 0; m < 32; m++) acc[m] = 0.f;
        for (int k4 = 0; k4 < 32; k4++) {
            float4 w = g_WinT4[k4 * NOUT + o];
#pragma unroll
            for (int m = 0; m < 32; m++) {
                float4 fv = *reinterpret_cast<const float4*>(&sf[m][k4 * 4]);
                acc[m] = fmaf(w.x, fv.x, acc[m]);
                acc[m] = fmaf(w.y, fv.y, acc[m]);
                acc[m] = fmaf(w.z, fv.z, acc[m]);
                acc[m] = fmaf(w.w, fv.w, acc[m]);
            }
        }
        if (o < GA) {
#pragma unroll
            for (int m = 0; m < 32; m++) {
                float v = acc[m];
#pragma unroll
                for (int j = 0; j < 3; j++) {
                    const float* E = g_E + j * QV * GA;
                    int lo = slo[j][m];
                    float fr = sfr[j][m];
                    float e0 = E[lo * GA + o];
                    float e1 = E[(lo + 1) * GA + o];
                    v += e0 + fr * (e1 - e0);
                }
                g_giA[(row0 + m) * GA + o] = v;
            }
        } else {
#pragma unroll
            for (int m = 0; m < 32; m++)
                g_giB[(row0 + m) * GB + (o - GA)] = acc[m];
        }
    }
}

// ---------------- GRU-A scan: 2-CTA cluster, 576 thr, reg/SMEM hybrid -----
// CTA rank owns 288 gate-rows (3 gates x 96 channels). Thread: row j=tid>>1,
// k-half s=tid&1 covers k in [s*96, s*96+96). 16 weight-float4 in registers,
// 8 streamed from SMEM. h double-buffered with bank-staggered halves
// (s=1 half at +112 floats) so mixed-s LDS.128 is one wavefront.
// Writers (activation) are the TOP warps (tid>=480) for arbiter priority.
__global__ void __cluster_dims__(2, 1, 1) __launch_bounds__(576, 1) k_gruA2r() {
    __shared__ __align__(16) float4 wsm[W_SMEM * 576];   // 36,864 B
    __shared__ __align__(16) float hbuf[2 * HSTRIDE];    // parity-doubled h
    __shared__ float s_u[192];                           // r,z pre-activations
    __shared__ float s_gin[96];
    __shared__ float s_ghn[96];

    int tid = threadIdx.x;
    unsigned rank = ctarank();
    unsigned peer = rank ^ 1u;
    int b = blockIdx.x >> 1;
    int j = tid >> 1;                   // row 0..287
    int s = tid & 1;                    // k-half
    int g = j / 96;                     // gate (warp-uniform: 6 warps/gate)
    int cl = j - g * 96;                // local channel
    int grow = g * ACH + (int)rank * 96 + cl;   // global gate row

    // weights: k4 = s*24 + i; first W_REG in registers, rest staged to SMEM
    float4 wreg[W_REG];
#pragma unroll
    for (int i = 0; i < W_REG; i++)
        wreg[i] = g_WhhA4[(s * 24 + i) * GA + grow];
#pragma unroll
    for (int i = 0; i < W_SMEM; i++)
        wsm[i * 576 + tid] = g_WhhA4[(s * 24 + W_REG + i) * GA + grow];

    for (int i = tid; i < 2 * HSTRIDE; i += 576) hbuf[i] = 0.f;
    __syncthreads();
    cluster_bar();

    int base = b * TT;
    float giv = 0.f;
    if (s == 0) giv = g_giA[base * GA + grow];

    // writer mapping (valid for tid >= 480)
    int aw = tid - 480;                               // 0..95
    int wchan = (int)rank * 96 + aw;                  // global channel
    int wslot = (int)rank * 112 + aw;                 // staggered buffer slot
    unsigned hbuf_addr = smem_u32(hbuf);

    for (int t = 0; t < TT; t++) {
        int row = base + t;
        float givn = 0.f;
        if (s == 0 && t + 1 < TT) givn = g_giA[(row + 1) * GA + grow];

        const float4* hc = reinterpret_cast<const float4*>(
            hbuf + (t & 1) * HSTRIDE + s * 112);
        float a0 = 0.f, a1 = 0.f, a2 = 0.f, a3 = 0.f;
#pragma unroll
        for (int i = 0; i < W_REG; i++) {
            float4 w = wreg[i];
            float4 hv = hc[i];
            a0 = fmaf(w.x, hv.x, a0);
            a1 = fmaf(w.y, hv.y, a1);
            a2 = fmaf(w.z, hv.z, a2);
            a3 = fmaf(w.w, hv.w, a3);
        }
#pragma unroll
        for (int i = 0; i < W_SMEM; i++) {
            float4 w = wsm[i * 576 + tid];
            float4 hv = hc[W_REG + i];
            a0 = fmaf(w.x, hv.x, a0);
            a1 = fmaf(w.y, hv.y, a1);
            a2 = fmaf(w.z, hv.z, a2);
            a3 = fmaf(w.w, hv.w, a3);
        }
        float v = (a0 + a1) + (a2 + a3);
        v += __shfl_xor_sync(0xffffffffu, v, 1);   // add partner half
        if (s == 0) {
            if (g < 2) s_u[j] = giv + v;           // j = g*96+cl
            else { s_gin[cl] = giv; s_ghn[cl] = v; }
        }
        __syncthreads();
        if (tid >= 480) {
            float r = sigm_f(s_u[aw]);
            float z = sigm_f(s_u[96 + aw]);
            float n = tanh_f(s_gin[aw] + r * s_ghn[aw]);
            int cur = (t & 1) * HSTRIDE, nxt = ((t + 1) & 1) * HSTRIDE;
            float hp = hbuf[cur + wslot];
            float hn = n + z * (hp - n);
            hbuf[nxt + wslot] = hn;
            st_peer_f32(hbuf_addr + (unsigned)(nxt + wslot) * 4u, peer, hn);
            g_hA[row * ACH + wchan] = hn;
        }
        cluster_bar();   // release local+peer h writes; acquire peer's
        giv = givn;
    }
}

// ---------------- gi_b += h_a @ W1^T : [BT,192] x [192,96] ----------------
__global__ void __launch_bounds__(96) k_giBadd() {
    __shared__ __align__(16) float sh[32][192];
    int tid = threadIdx.x;
    int row0 = blockIdx.x * 32;
    for (int i = tid; i < 32 * 192; i += 96)
        sh[i / 192][i % 192] = g_hA[row0 * 192 + i];
    __syncthreads();
    int o = tid;
    float acc[32];
#pragma unroll
    for (int m = 0; m < 32; m++) acc[m] = 0.f;
    for (int k4 = 0; k4 < 48; k4++) {
        float4 w = g_W1T4[k4 * GB + o];
#pragma unroll
        for (int m = 0; m < 32; m++) {
            float4 hv = *reinterpret_cast<const float4*>(&sh[m][k4 * 4]);
            acc[m] = fmaf(w.x, hv.x, acc[m]);
            acc[m] = fmaf(w.y, hv.y, acc[m]);
            acc[m] = fmaf(w.z, hv.z, acc[m]);
            acc[m] = fmaf(w.w, hv.w, acc[m]);
        }
    }
#pragma unroll
    for (int m = 0; m < 32; m++) {
        int idx = (row0 + m) * GB + o;
        g_giB[idx] += acc[m];
    }
}

// ---------------- GRU-B scan: 32 blocks, 96 threads, depth-4 gi prefetch --
__global__ void __launch_bounds__(96) k_gruB(const float* __restrict__ whhb) {
    __shared__ __align__(16) float4 wt4[8 * GB];
    __shared__ __align__(16) float h[BCH];
    __shared__ float gh[GB];
    __shared__ float gi[GB];
    int tid = threadIdx.x;
    int b = blockIdx.x;
    for (int i = tid; i < 8 * GB; i += 96) {
        int k4 = i / GB, o = i % GB;
        const float* src = whhb + o * 32 + 4 * k4;
        wt4[i] = make_float4(src[0], src[1], src[2], src[3]);
    }
    if (tid < BCH) h[tid] = 0.f;
    __syncthreads();
    int base = b * TT;
    float pre[4];
#pragma unroll
    for (int j = 0; j < 4; j++)
        pre[j] = g_giB[(base + j) * GB + tid];

    for (int t = 0; t < TT; t += 4) {
#pragma unroll
        for (int j = 0; j < 4; j++) {
            int tt = t + j;
            int row = base + tt;
            float givn = (tt + 4 < TT) ? g_giB[(row + 4) * GB + tid] : 0.f;
            float a0 = 0.f, a1 = 0.f;
#pragma unroll
            for (int k4 = 0; k4 < 8; k4++) {
                float4 w  = wt4[k4 * GB + tid];
                float4 hv = *reinterpret_cast<const float4*>(&h[4 * k4]);
                a0 = fmaf(w.x, hv.x, a0);
                a0 = fmaf(w.y, hv.y, a0);
                a1 = fmaf(w.z, hv.z, a1);
                a1 = fmaf(w.w, hv.w, a1);
            }
            gh[tid] = a0 + a1;
            gi[tid] = pre[j];
            __syncthreads();
            if (tid < BCH) {
                float r = sigm_f(gi[tid] + gh[tid]);
                float z = sigm_f(gi[BCH + tid] + gh[BCH + tid]);
                float n = tanh_f(gi[2 * BCH + tid] + r * gh[2 * BCH + tid]);
                float hn = n + z * (h[tid] - n);
                h[tid] = hn;
                g_hB[row * BCH + tid] = hn;
            }
            __syncthreads();
            pre[j] = givn;
        }
    }
}

// ---------------- output: tanh(h_b @ fc_w^T + b) * a, pair-sum ------------
__global__ void __launch_bounds__(256) k_out(const float* __restrict__ av,
                                             const float* __restrict__ fcb,
                                             float* __restrict__ out) {
    __shared__ __align__(16) float shb[32][32];
    int tid = threadIdx.x;
    int row0 = blockIdx.x * 32;
    for (int i = tid; i < 32 * 32; i += 256)
        shb[i >> 5][i & 31] = g_hB[row0 * 32 + i];
    __syncthreads();
    int q = tid;
    float2 wreg[32];
#pragma unroll
    for (int k = 0; k < 32; k++)
        wreg[k] = *reinterpret_cast<const float2*>(g_fcwT + k * 512 + 2 * q);
    float b0 = fcb[2 * q], b1 = fcb[2 * q + 1];
    float av0 = av[2 * q], av1 = av[2 * q + 1];
    for (int m = 0; m < 32; m++) {
        float d0 = b0, d1 = b1;
        const float4* hp = reinterpret_cast<const float4*>(shb[m]);
#pragma unroll
        for (int k4 = 0; k4 < 8; k4++) {
            float4 hv = hp[k4];
            d0 = fmaf(hv.x, wreg[4 * k4 + 0].x, d0);
            d0 = fmaf(hv.y, wreg[4 * k4 + 1].x, d0);
            d0 = fmaf(hv.z, wreg[4 * k4 + 2].x, d0);
            d0 = fmaf(hv.w, wreg[4 * k4 + 3].x, d0);
            d1 = fmaf(hv.x, wreg[4 * k4 + 0].y, d1);
            d1 = fmaf(hv.y, wreg[4 * k4 + 1].y, d1);
            d1 = fmaf(hv.z, wreg[4 * k4 + 2].y, d1);
            d1 = fmaf(hv.w, wreg[4 * k4 + 3].y, d1);
        }
        float t0 = tanh_f(d0);
        float t1 = tanh_f(d1);
        out[(row0 + m) * 256 + q] = av0 * t0 + av1 * t1;
    }
}

// ---------------- launch ----------------
extern "C" void kernel_launch(void* const* d_in, const int* in_sizes, int n_in,
                              void* d_out, int out_size) {
    const float* f    = (const float*)d_in[0];
    const float* p    = (const float*)d_in[1];
    const float* sp   = (const float*)d_in[2];
    const float* ep   = (const float*)d_in[3];
    const float* emb  = (const float*)d_in[4];
    const float* wiha = (const float*)d_in[5];
    const float* whha = (const float*)d_in[6];
    const float* wihb = (const float*)d_in[7];
    const float* whhb = (const float*)d_in[8];
    const float* av   = (const float*)d_in[9];
    const float* fcw  = (const float*)d_in[10];
    const float* fcb  = (const float*)d_in[11];
    float* out = (float*)d_out;

    k_prep1<<<256, 256>>>(emb, wiha, whha, wihb, fcw);
    k_prep2<<<1728, 256>>>(wiha);
    k_giA<<<BT / 32, 256>>>(f, p, sp, ep);
    k_gruA2r<<<2 * NB, 576>>>();
    k_giBadd<<<BT / 32, GB>>>();
    k_gruB<<<NB, GB>>>(whhb);
    k_out<<<BT / 32, 256>>>(av, fcb, out);
}